// round 3
// baseline (speedup 1.0000x reference)
#include <cuda_runtime.h>
#include <cuda_bf16.h>

// Problem constants
#define NW   8192
#define NTOK 64
#define CDIM 180
#define HEADS 6
#define HD   30
#define NW_PER_IMG 1024
#define KDIM 180          // GEMM K for both GEMMs
#define KPAD 184          // padded to multiple of 8
#define LDS_STRIDE 188    // smem row stride (conflict-free for frag loads)
#define KSTEPS 23         // 184 / 8

// Scratch (allocation-guard-safe: __device__ globals)
__device__ float g_qkv[(long long)NW * NTOK * (3 * CDIM)];   // [nW*N, 540]
__device__ float g_att[(long long)NW * NTOK * CDIM];         // [nW*N, 180]

// ---------------------------------------------------------------------------
// tf32 helpers
// ---------------------------------------------------------------------------
__device__ __forceinline__ float f2tf32(float x) {
    unsigned u;
    asm("cvt.rna.tf32.f32 %0, %1;" : "=r"(u) : "f"(x));
    return __uint_as_float(u);
}

__device__ __forceinline__ void mma_tf32(float d[4], const float a[4], const float b[2]) {
    const unsigned* A = reinterpret_cast<const unsigned*>(a);
    const unsigned* B = reinterpret_cast<const unsigned*>(b);
    asm volatile(
        "mma.sync.aligned.m16n8k8.row.col.f32.tf32.tf32.f32 "
        "{%0,%1,%2,%3},{%4,%5,%6,%7},{%8,%9},{%0,%1,%2,%3};\n"
        : "+f"(d[0]), "+f"(d[1]), "+f"(d[2]), "+f"(d[3])
        : "r"(A[0]), "r"(A[1]), "r"(A[2]), "r"(A[3]), "r"(B[0]), "r"(B[1]));
}

// ---------------------------------------------------------------------------
// GEMM (TN) via tf32 mma: C[M,N] = A[M,180] @ B[N,180]^T + bias[N]
// CTA tile 128x64, entire K strip staged in smem once (144 KB), 256 threads.
// 8 warps: 4 along M (32 rows each) x 2 along N (32 cols each).
// Each warp: 2 m-tiles (16) x 4 n-tiles (8) = 8 mma per k8-step, 23 steps.
// ---------------------------------------------------------------------------
__global__ __launch_bounds__(256, 1) void mma_gemm_tn(
    const float* __restrict__ A, const float* __restrict__ B,
    const float* __restrict__ bias, float* __restrict__ C, int N)
{
    extern __shared__ float smem[];
    float* sA = smem;                       // [128][LDS_STRIDE]
    float* sB = smem + 128 * LDS_STRIDE;    // [64][LDS_STRIDE]

    const int tid = threadIdx.x;
    const int row0 = blockIdx.y * 128;
    const int col0 = blockIdx.x * 64;

    // Stage A strip: 128 rows x 184 cols (cols 180..183 zero), tf32-converted.
    for (int i = tid; i < 128 * 46; i += 256) {
        int r = i / 46, c4 = i % 46;
        float4 v = make_float4(0.f, 0.f, 0.f, 0.f);
        if (c4 < 45) v = *(const float4*)(A + (row0 + r) * KDIM + c4 * 4);
        float* dst = sA + r * LDS_STRIDE + c4 * 4;
        dst[0] = f2tf32(v.x); dst[1] = f2tf32(v.y);
        dst[2] = f2tf32(v.z); dst[3] = f2tf32(v.w);
    }
    // Stage B strip: 64 rows (guarded by N) x 184 cols.
    for (int i = tid; i < 64 * 46; i += 256) {
        int r = i / 46, c4 = i % 46;
        int n = col0 + r;
        float4 v = make_float4(0.f, 0.f, 0.f, 0.f);
        if (n < N && c4 < 45) v = *(const float4*)(B + n * KDIM + c4 * 4);
        float* dst = sB + r * LDS_STRIDE + c4 * 4;
        dst[0] = f2tf32(v.x); dst[1] = f2tf32(v.y);
        dst[2] = f2tf32(v.z); dst[3] = f2tf32(v.w);
    }
    __syncthreads();

    const int warp = tid >> 5;
    const int lane = tid & 31;
    const int wm = warp & 3;          // 0..3 -> 32 rows each
    const int wn = warp >> 2;         // 0..1 -> 32 cols each
    const int g = lane >> 2;          // groupID 0..7
    const int t = lane & 3;           // threadID_in_group 0..3

    float acc[2][4][4];
#pragma unroll
    for (int mt = 0; mt < 2; mt++)
#pragma unroll
        for (int nt = 0; nt < 4; nt++)
#pragma unroll
            for (int e = 0; e < 4; e++) acc[mt][nt][e] = 0.f;

#pragma unroll 1
    for (int ks = 0; ks < KSTEPS; ks++) {
        const int kb = ks * 8;
        float a[2][4];
#pragma unroll
        for (int mt = 0; mt < 2; mt++) {
            int r0 = (wm * 32 + mt * 16 + g) * LDS_STRIDE + kb;
            a[mt][0] = sA[r0 + t];
            a[mt][1] = sA[r0 + 8 * LDS_STRIDE + t];
            a[mt][2] = sA[r0 + t + 4];
            a[mt][3] = sA[r0 + 8 * LDS_STRIDE + t + 4];
        }
        float b[4][2];
#pragma unroll
        for (int nt = 0; nt < 4; nt++) {
            int rn = (wn * 32 + nt * 8 + g) * LDS_STRIDE + kb;
            b[nt][0] = sB[rn + t];
            b[nt][1] = sB[rn + t + 4];
        }
#pragma unroll
        for (int mt = 0; mt < 2; mt++)
#pragma unroll
            for (int nt = 0; nt < 4; nt++)
                mma_tf32(acc[mt][nt], a[mt], b[nt]);
    }

    // Epilogue: c0,c1 at (g, 2t..2t+1), c2,c3 at (g+8, 2t..2t+1)
#pragma unroll
    for (int mt = 0; mt < 2; mt++) {
#pragma unroll
        for (int nt = 0; nt < 4; nt++) {
            int row = row0 + wm * 32 + mt * 16 + g;
            int col = col0 + wn * 32 + nt * 8 + 2 * t;
            if (col < N) {
                float b0 = bias[col], b1 = bias[col + 1];
                float2 v0 = make_float2(acc[mt][nt][0] + b0, acc[mt][nt][1] + b1);
                float2 v1 = make_float2(acc[mt][nt][2] + b0, acc[mt][nt][3] + b1);
                *(float2*)(C + (long long)row * N + col) = v0;
                *(float2*)(C + (long long)(row + 8) * N + col) = v1;
            }
        }
    }
}

// ---------------------------------------------------------------------------
// Attention: one block per (window, head), 64 threads = 1 query row each.
// Single pass, no max-subtraction (scores provably small), online accumulate.
// Mask tile + per-head RPB row staged in smem.
// ---------------------------------------------------------------------------
__global__ __launch_bounds__(64) void attn_kernel(
    const float* __restrict__ qkv, const float* __restrict__ mask,
    const float* __restrict__ rpb, float* __restrict__ out)
{
    const int w = blockIdx.x;      // window
    const int h = blockIdx.y;      // head
    const int n = threadIdx.x;     // query token

    __shared__ float ks[NTOK][32];
    __shared__ float vs[NTOK][32];
    __shared__ float ms[NTOK][65];   // padded: bank = (n + m) % 32
    __shared__ float rpbh[225];

    const float scale = rsqrtf((float)HD);
    const long long base = (long long)(w * NTOK + n) * (3 * CDIM);

    const float* krow = qkv + base + CDIM + h * HD;
    const float* vrow = qkv + base + 2 * CDIM + h * HD;
#pragma unroll
    for (int d = 0; d < HD; d++) { ks[n][d] = krow[d]; vs[n][d] = vrow[d]; }
    ks[n][30] = 0.f; ks[n][31] = 0.f;
    vs[n][30] = 0.f; vs[n][31] = 0.f;

    // Stage per-head RPB row (225 floats)
    for (int i = n; i < 225; i += NTOK) rpbh[i] = rpb[i * HEADS + h];

    // Stage mask tile (coalesced float4 reads)
    const int wi = w & (NW_PER_IMG - 1);
    const float4* mbase = (const float4*)(mask + (long long)wi * NTOK * NTOK);
    for (int i = n; i < NTOK * NTOK / 4; i += NTOK) {
        float4 v = mbase[i];
        int r = i >> 4, c = (i & 15) * 4;
        ms[r][c + 0] = v.x; ms[r][c + 1] = v.y;
        ms[r][c + 2] = v.z; ms[r][c + 3] = v.w;
    }

    float q[32];
    const float* qrow = qkv + base + h * HD;
#pragma unroll
    for (int d = 0; d < HD; d++) q[d] = qrow[d] * scale;
    q[30] = 0.f; q[31] = 0.f;

    __syncthreads();

    const int i1 = n >> 3, j1 = n & 7;

    float o[32];
#pragma unroll
    for (int d = 0; d < 32; d++) o[d] = 0.f;
    float sum = 0.f;

#pragma unroll 4
    for (int m = 0; m < NTOK; m++) {
        float acc = 0.f;
#pragma unroll
        for (int dq = 0; dq < 8; dq++) {
            float4 k4 = *(const float4*)&ks[m][dq * 4];
            acc = fmaf(q[dq * 4 + 0], k4.x, acc);
            acc = fmaf(q[dq * 4 + 1], k4.y, acc);
            acc = fmaf(q[dq * 4 + 2], k4.z, acc);
            acc = fmaf(q[dq * 4 + 3], k4.w, acc);
        }
        int i2 = m >> 3, j2 = m & 7;
        int idx = (i1 - i2 + 7) * 15 + (j1 - j2 + 7);
        acc += rpbh[idx] + ms[n][m];

        float p = __expf(acc);
        sum += p;
#pragma unroll
        for (int dq = 0; dq < 8; dq++) {
            float4 v4 = *(const float4*)&vs[m][dq * 4];
            o[dq * 4 + 0] = fmaf(p, v4.x, o[dq * 4 + 0]);
            o[dq * 4 + 1] = fmaf(p, v4.y, o[dq * 4 + 1]);
            o[dq * 4 + 2] = fmaf(p, v4.z, o[dq * 4 + 2]);
            o[dq * 4 + 3] = fmaf(p, v4.w, o[dq * 4 + 3]);
        }
    }

    const float inv = 1.f / sum;
    float* orow = out + (long long)(w * NTOK + n) * CDIM + h * HD;
#pragma unroll
    for (int d = 0; d < HD; d++) orow[d] = o[d] * inv;
}

// ---------------------------------------------------------------------------
extern "C" void kernel_launch(void* const* d_in, const int* in_sizes, int n_in,
                              void* d_out, int out_size)
{
    const float* x      = (const float*)d_in[0];
    const float* mask   = (const float*)d_in[1];
    const float* qkv_w  = (const float*)d_in[2];
    const float* qkv_b  = (const float*)d_in[3];
    const float* proj_w = (const float*)d_in[4];
    const float* proj_b = (const float*)d_in[5];
    const float* rpb    = (const float*)d_in[6];
    float* out = (float*)d_out;

    void* p_qkv = nullptr;
    void* p_att = nullptr;
    cudaGetSymbolAddress(&p_qkv, g_qkv);
    cudaGetSymbolAddress(&p_att, g_att);
    float* qkv = (float*)p_qkv;
    float* att = (float*)p_att;

    const int M = NW * NTOK;                         // 524288
    const int smem_bytes = (128 + 64) * LDS_STRIDE * sizeof(float);  // 144384

    static bool attr_set = false;
    if (!attr_set) {
        cudaFuncSetAttribute(mma_gemm_tn,
                             cudaFuncAttributeMaxDynamicSharedMemorySize,
                             smem_bytes);
        attr_set = true;
    }

    // 1) QKV projection: [M,180] @ [540,180]^T + b -> [M,540]
    {
        dim3 grid((3 * CDIM + 63) / 64, M / 128);
        mma_gemm_tn<<<grid, 256, smem_bytes>>>(x, qkv_w, qkv_b, qkv, 3 * CDIM);
    }

    // 2) Attention per (window, head)
    {
        dim3 grid(NW, HEADS);
        attn_kernel<<<grid, NTOK>>>(qkv, mask, rpb, att);
    }

    // 3) Output projection: [M,180] @ [180,180]^T + b -> [M,180]
    {
        dim3 grid((CDIM + 63) / 64, M / 128);
        mma_gemm_tn<<<grid, 256, smem_bytes>>>(att, proj_w, proj_b, out, CDIM);
    }
}

// round 4
// speedup vs baseline: 3.8365x; 3.8365x over previous
#include <cuda_runtime.h>
#include <cuda_bf16.h>
#include <cstdint>

// Problem constants
#define NW   8192
#define NTOK 64
#define CDIM 180
#define HEADS 6
#define HD   30
#define NW_PER_IMG 1024

// Scratch (allocation-guard-safe: __device__ globals)
__device__ float g_qkv[(long long)NW * NTOK * (3 * CDIM)];   // [nW*N, 540]
__device__ float g_att[(long long)NW * NTOK * CDIM];         // [nW*N, 180]

// ===========================================================================
// f32x2 paired-fp32 helpers (Blackwell)
// ===========================================================================
__device__ __forceinline__ unsigned long long fma2(unsigned long long a,
                                                   unsigned long long b,
                                                   unsigned long long c) {
    unsigned long long d;
    asm("fma.rn.f32x2 %0, %1, %2, %3;" : "=l"(d) : "l"(a), "l"(b), "l"(c));
    return d;
}
__device__ __forceinline__ unsigned long long add2(unsigned long long a,
                                                   unsigned long long b) {
    unsigned long long d;
    asm("add.rn.f32x2 %0, %1, %2;" : "=l"(d) : "l"(a), "l"(b));
    return d;
}
__device__ __forceinline__ unsigned long long mul2(unsigned long long a,
                                                   unsigned long long b) {
    unsigned long long d;
    asm("mul.rn.f32x2 %0, %1, %2;" : "=l"(d) : "l"(a), "l"(b));
    return d;
}
__device__ __forceinline__ unsigned long long pack2(float lo, float hi) {
    unsigned long long r;
    asm("mov.b64 %0, {%1, %2};" : "=l"(r) : "f"(lo), "f"(hi));
    return r;
}
__device__ __forceinline__ void unpack2(float& lo, float& hi, unsigned long long v) {
    asm("mov.b64 {%0, %1}, %2;" : "=f"(lo), "=f"(hi) : "l"(v));
}

// ===========================================================================
// tf32 mma m16n8k8
// ===========================================================================
__device__ __forceinline__ void mma_tf32(float d[4], const float a[4], const float b[2]) {
    const unsigned* A = reinterpret_cast<const unsigned*>(a);
    const unsigned* B = reinterpret_cast<const unsigned*>(b);
    asm volatile(
        "mma.sync.aligned.m16n8k8.row.col.f32.tf32.tf32.f32 "
        "{%0,%1,%2,%3},{%4,%5,%6,%7},{%8,%9},{%0,%1,%2,%3};\n"
        : "+f"(d[0]), "+f"(d[1]), "+f"(d[2]), "+f"(d[3])
        : "r"(A[0]), "r"(A[1]), "r"(A[2]), "r"(A[3]), "r"(B[0]), "r"(B[1]));
}

__device__ __forceinline__ void cp_async16(unsigned dst, const void* src, int src_bytes) {
    asm volatile("cp.async.cg.shared.global [%0], [%1], 16, %2;\n"
                 :: "r"(dst), "l"(src), "r"(src_bytes));
}
__device__ __forceinline__ void cp_commit() {
    asm volatile("cp.async.commit_group;\n" ::: "memory");
}
__device__ __forceinline__ void cp_wait1() {
    asm volatile("cp.async.wait_group 1;\n" ::: "memory");
}

// ===========================================================================
// GEMM (TN): C[M,N] = A[M,180] @ B[N,180]^T + bias[N]
// BM=128, BN=128, BK=32, 3-stage cp.async pipeline, 256 threads, tf32 mma.
// K padded to 192 (6 iters), zero-filled via cp.async zfill.
// ===========================================================================
#define GROWS 36                    // smem row stride (words): mult of 4, conflict-free
#define GSTAGE_WORDS (256 * GROWS)  // A(128 rows) + B(128 rows) per stage
#define GNITER 6

__global__ __launch_bounds__(256, 2) void mma_gemm_tn(
    const float* __restrict__ A, const float* __restrict__ B,
    const float* __restrict__ bias, float* __restrict__ C, int N)
{
    extern __shared__ float sm[];
    const int tid = threadIdx.x;
    const int row0 = blockIdx.y * 128;
    const int col0 = blockIdx.x * 128;

    const unsigned sbase = (unsigned)__cvta_generic_to_shared(sm);

    // ---- staging lambda (stage s, k-iteration ki) ----
    auto stage_load = [&](int s, int ki) {
        const int k0 = ki * 32;
        const unsigned stW = sbase + (unsigned)(s * GSTAGE_WORDS) * 4u;
#pragma unroll
        for (int j = 0; j < 8; j++) {
            int idx = tid + j * 256;            // 0..2047
            int r  = (idx & 1023) >> 3;         // row 0..127
            int c4 = idx & 7;
            int gk = k0 + c4 * 4;
            int gkc = gk <= 176 ? gk : 176;
            if (idx < 1024) {
                int bytes = (gk <= 176) ? 16 : 0;
                const float* src = A + (size_t)(row0 + r) * CDIM + gkc;
                cp_async16(stW + (unsigned)(r * GROWS + c4 * 4) * 4u, src, bytes);
            } else {
                int nn = col0 + r;
                int ok = (nn < N) && (gk <= 176);
                const float* src = B + (size_t)(ok ? nn : 0) * CDIM + gkc;
                cp_async16(stW + (unsigned)(128 * GROWS + r * GROWS + c4 * 4) * 4u,
                           src, ok ? 16 : 0);
            }
        }
    };

    stage_load(0, 0); cp_commit();
    stage_load(1, 1); cp_commit();
    cp_wait1();
    __syncthreads();

    const int warp = tid >> 5;
    const int lane = tid & 31;
    const int wm = warp & 1;          // 0..1 -> 64 rows
    const int wn = warp >> 1;         // 0..3 -> 32 cols
    const int g = lane >> 2;
    const int t = lane & 3;

    float acc[4][4][4];
#pragma unroll
    for (int mt = 0; mt < 4; mt++)
#pragma unroll
        for (int nt = 0; nt < 4; nt++)
#pragma unroll
            for (int e = 0; e < 4; e++) acc[mt][nt][e] = 0.f;

#pragma unroll 1
    for (int ks = 0; ks < GNITER; ks++) {
        if (ks + 2 < GNITER) stage_load((ks + 2) % 3, ks + 2);
        cp_commit();

        const float* sA = sm + (ks % 3) * GSTAGE_WORDS;
        const float* sB = sA + 128 * GROWS;

#pragma unroll
        for (int step = 0; step < 4; step++) {
            const int kb = step * 8;
            float a[4][4], b[4][2];
#pragma unroll
            for (int mt = 0; mt < 4; mt++) {
                int base = (wm * 64 + mt * 16 + g) * GROWS + kb + t;
                a[mt][0] = sA[base];
                a[mt][1] = sA[base + 8 * GROWS];
                a[mt][2] = sA[base + 4];
                a[mt][3] = sA[base + 8 * GROWS + 4];
            }
#pragma unroll
            for (int nt = 0; nt < 4; nt++) {
                int bb = (wn * 32 + nt * 8 + g) * GROWS + kb + t;
                b[nt][0] = sB[bb];
                b[nt][1] = sB[bb + 4];
            }
#pragma unroll
            for (int mt = 0; mt < 4; mt++)
#pragma unroll
                for (int nt = 0; nt < 4; nt++)
                    mma_tf32(acc[mt][nt], a[mt], b[nt]);
        }
        cp_wait1();
        __syncthreads();
    }

    // Epilogue
#pragma unroll
    for (int mt = 0; mt < 4; mt++) {
#pragma unroll
        for (int nt = 0; nt < 4; nt++) {
            int row = row0 + wm * 64 + mt * 16 + g;
            int col = col0 + wn * 32 + nt * 8 + 2 * t;
            if (col < N) {
                float b0 = bias[col], b1 = bias[col + 1];
                float2 v0 = make_float2(acc[mt][nt][0] + b0, acc[mt][nt][1] + b1);
                float2 v1 = make_float2(acc[mt][nt][2] + b0, acc[mt][nt][3] + b1);
                *(float2*)(C + (size_t)row * N + col) = v0;
                *(float2*)(C + (size_t)(row + 8) * N + col) = v1;
            }
        }
    }
}

// ===========================================================================
// Attention: one block per (window, head-pair). 128 threads: hl=tid/64 picks
// the head within the pair, n=tid%64 the query row. All global I/O staged
// through smem with coalesced float4. Math in paired fp32 (f32x2).
// smem layout (floats):
//   [0)      sQ [2][64][36]   (4608)  -- reused as output staging
//   [4608)   sK [2][64][36]   (4608)
//   [9216)   sV [2][64][36]   (4608)
//   [13824)  sM [64][65]      (4160)
//   [17984)  sR [2][225]      (450)
// total 18434 floats = 73736 B
// ===========================================================================
#define ATT_SMEM_FLOATS 18434

__global__ __launch_bounds__(128) void attn_kernel(
    const float* __restrict__ qkv, const float* __restrict__ mask,
    const float* __restrict__ rpb, float* __restrict__ out)
{
    extern __shared__ float sm[];
    float* sM = sm + 13824;
    float* sR = sm + 17984;

    const int w = blockIdx.x;
    const int pair = blockIdx.y;
    const int h0 = pair * 2;
    const int tid = threadIdx.x;

    // ---- stage q/k/v slices (coalesced) ----
    for (int i = tid; i < 2880; i += 128) {
        int arr = i / 960;                   // 0=q 1=k 2=v
        int rem = i - arr * 960;
        int r = rem / 15, c4 = rem - r * 15;
        float4 v = *(const float4*)(qkv + (size_t)(w * NTOK + r) * (3 * CDIM)
                                    + arr * CDIM + h0 * HD + c4 * 4);
        float* dst = sm + arr * 4608;
        const float* vf = (const float*)&v;
#pragma unroll
        for (int j = 0; j < 4; j++) {
            int d = c4 * 4 + j;
            int hl = d >= 30;
            dst[hl * 2304 + r * GROWS + (d - 30 * hl)] = vf[j];
        }
    }
    // zero pad d=30,31
    for (int i = tid; i < 768; i += 128) {
        int arr = i / 256;
        int rem = i - arr * 256;
        int hl = rem >> 7;
        int r = (rem & 127) >> 1;
        sm[arr * 4608 + hl * 2304 + r * GROWS + 30 + (rem & 1)] = 0.f;
    }
    // stage mask tile
    {
        const int wi = w & (NW_PER_IMG - 1);
        const float4* mbase = (const float4*)(mask + (size_t)wi * NTOK * NTOK);
        for (int i = tid; i < 1024; i += 128) {
            float4 v = mbase[i];
            int r = i >> 4, c = (i & 15) * 4;
            sM[r * 65 + c + 0] = v.x; sM[r * 65 + c + 1] = v.y;
            sM[r * 65 + c + 2] = v.z; sM[r * 65 + c + 3] = v.w;
        }
    }
    // stage rpb rows for both heads
    for (int i = tid; i < 450; i += 128) {
        int hl = i / 225, idx = i - hl * 225;
        sR[hl * 225 + idx] = rpb[idx * HEADS + h0 + hl];
    }
    __syncthreads();

    const int hl = tid >> 6;
    const int n = tid & 63;

    // q into packed regs, pre-scaled
    const float scale = rsqrtf((float)HD);
    const unsigned long long scale2 = pack2(scale, scale);
    unsigned long long q2[16];
    {
        const float* qrow = sm + hl * 2304 + n * GROWS;
#pragma unroll
        for (int dq = 0; dq < 8; dq++) {
            ulonglong2 tq = *(const ulonglong2*)(qrow + dq * 4);
            q2[2 * dq + 0] = mul2(tq.x, scale2);
            q2[2 * dq + 1] = mul2(tq.y, scale2);
        }
    }

    const float* krow0 = sm + 4608 + hl * 2304;
    const float* vrow0 = sm + 9216 + hl * 2304;
    const float* rph = sR + hl * 225;
    const float* mrow = sM + n * 65;
    const int i1 = n >> 3, j1 = n & 7;

    unsigned long long o2[16];
#pragma unroll
    for (int j = 0; j < 16; j++) o2[j] = 0ull;
    float osum = 0.f;

#pragma unroll 2
    for (int m = 0; m < NTOK; m++) {
        const float* kr = krow0 + m * GROWS;
        unsigned long long a0 = 0ull, a1 = 0ull, a2 = 0ull, a3 = 0ull;
#pragma unroll
        for (int dq = 0; dq < 4; dq++) {
            ulonglong2 k0 = *(const ulonglong2*)(kr + dq * 8);
            ulonglong2 k1 = *(const ulonglong2*)(kr + dq * 8 + 4);
            a0 = fma2(q2[4 * dq + 0], k0.x, a0);
            a1 = fma2(q2[4 * dq + 1], k0.y, a1);
            a2 = fma2(q2[4 * dq + 2], k1.x, a2);
            a3 = fma2(q2[4 * dq + 3], k1.y, a3);
        }
        unsigned long long asum = add2(add2(a0, a1), add2(a2, a3));
        float slo, shi;
        unpack2(slo, shi, asum);
        int i2 = m >> 3, j2 = m & 7;
        int idx = (i1 - i2 + 7) * 15 + (j1 - j2 + 7);
        float s = slo + shi + rph[idx] + mrow[m];

        float p = __expf(s);
        osum += p;
        unsigned long long p2 = pack2(p, p);

        const float* vr = vrow0 + m * GROWS;
#pragma unroll
        for (int dq = 0; dq < 4; dq++) {
            ulonglong2 v0 = *(const ulonglong2*)(vr + dq * 8);
            ulonglong2 v1 = *(const ulonglong2*)(vr + dq * 8 + 4);
            o2[4 * dq + 0] = fma2(p2, v0.x, o2[4 * dq + 0]);
            o2[4 * dq + 1] = fma2(p2, v0.y, o2[4 * dq + 1]);
            o2[4 * dq + 2] = fma2(p2, v1.x, o2[4 * dq + 2]);
            o2[4 * dq + 3] = fma2(p2, v1.y, o2[4 * dq + 3]);
        }
    }

    __syncthreads();   // done reading sQ (q already in regs) -> safe to reuse

    {
        const float inv = 1.f / osum;
        const unsigned long long inv2 = pack2(inv, inv);
        float* od = sm + hl * 2304 + n * GROWS;
#pragma unroll
        for (int j = 0; j < 15; j++) {
            unsigned long long r = mul2(o2[j], inv2);
            *(unsigned long long*)(od + 2 * j) = r;
        }
    }
    __syncthreads();

    // coalesced write-out
    for (int i = tid; i < 960; i += 128) {
        int r = i / 15, c4 = i - r * 15;
        float4 v;
        float* vf = (float*)&v;
#pragma unroll
        for (int j = 0; j < 4; j++) {
            int d = c4 * 4 + j;
            int hh = d >= 30;
            vf[j] = sm[hh * 2304 + r * GROWS + (d - 30 * hh)];
        }
        *(float4*)(out + (size_t)(w * NTOK + r) * CDIM + h0 * HD + c4 * 4) = v;
    }
}

// ===========================================================================
extern "C" void kernel_launch(void* const* d_in, const int* in_sizes, int n_in,
                              void* d_out, int out_size)
{
    const float* x      = (const float*)d_in[0];
    const float* mask   = (const float*)d_in[1];
    const float* qkv_w  = (const float*)d_in[2];
    const float* qkv_b  = (const float*)d_in[3];
    const float* proj_w = (const float*)d_in[4];
    const float* proj_b = (const float*)d_in[5];
    const float* rpb    = (const float*)d_in[6];
    float* out = (float*)d_out;

    void* p_qkv = nullptr;
    void* p_att = nullptr;
    cudaGetSymbolAddress(&p_qkv, g_qkv);
    cudaGetSymbolAddress(&p_att, g_att);
    float* qkv = (float*)p_qkv;
    float* att = (float*)p_att;

    const int M = NW * NTOK;                              // 524288
    const int gemm_smem = 3 * GSTAGE_WORDS * sizeof(float);   // 110592
    const int attn_smem = ATT_SMEM_FLOATS * sizeof(float);    // 73736

    static bool attr_set = false;
    if (!attr_set) {
        cudaFuncSetAttribute(mma_gemm_tn,
                             cudaFuncAttributeMaxDynamicSharedMemorySize, gemm_smem);
        cudaFuncSetAttribute(attn_kernel,
                             cudaFuncAttributeMaxDynamicSharedMemorySize, attn_smem);
        attr_set = true;
    }

    // 1) QKV projection: [M,180] @ [540,180]^T + b -> [M,540]
    {
        dim3 grid((3 * CDIM + 127) / 128, M / 128);
        mma_gemm_tn<<<grid, 256, gemm_smem>>>(x, qkv_w, qkv_b, qkv, 3 * CDIM);
    }

    // 2) Attention per (window, head-pair)
    {
        dim3 grid(NW, HEADS / 2);
        attn_kernel<<<grid, 128, attn_smem>>>(qkv, mask, rpb, att);
    }

    // 3) Output projection: [M,180] @ [180,180]^T + b -> [M,180]
    {
        dim3 grid((CDIM + 127) / 128, M / 128);
        mma_gemm_tn<<<grid, 256, gemm_smem>>>(att, proj_w, proj_b, out, CDIM);
    }
}